// round 7
// baseline (speedup 1.0000x reference)
#include <cuda_runtime.h>

// IDWT1D (Haar synthesis) — 2-tap banded A collapses to a streaming butterfly.
//
//   out[b,2i  ,c] = A[0,0]*x[b,i,c] + A[M,0]*x[b,i,C+c]
//   out[b,2i+1,c] = A[0,1]*x[b,i,c] + A[M,1]*x[b,i,C+c]
//
// Input row (b,i) = 32 contiguous floats [approx16|detail16]; the two output
// rows occupy the SAME 32-float span. Item = one float4-pair (a,d).
//
// History:
//  R3: 1 item/thr, 524K thr (>=2 waves), MLP 2          -> 7.9us
//  R4: 8 loads/thr, regs=32 serialized, 131K thr        -> 14us
//  R6: 2 items/thr, 262K thr (1 wave) but regs=34 ->
//      ptxas serialized the two items, MLP still 2      -> 9.0us
//  R7: same single-wave geometry, but (a) launch_bounds(256,6) gives ptxas a
//      42-reg budget so all 4 LDG.128 can be live at once, (b) all-32-bit
//      index math (R3 showed 13% alu from 64-bit IMAD) frees regs + issue.

__global__ void __launch_bounds__(256, 6)
idwt_haar_x2_kernel(const float4* __restrict__ xin,
                    const float* __restrict__ A,
                    float4* __restrict__ o,
                    unsigned n_items,          // total float4-pairs = B*M*4
                    unsigned highpass_row)     // M*N: flat index of A[M,0]
{
    const float h00 = __ldg(&A[0]);                 // A[0,0]
    const float h01 = __ldg(&A[1]);                 // A[0,1]
    const float h10 = __ldg(&A[highpass_row]);      // A[M,0]
    const float h11 = __ldg(&A[highpass_row + 1]);  // A[M,1]

    const unsigned gsize = gridDim.x * blockDim.x;
    const unsigned it0   = blockIdx.x * blockDim.x + threadIdx.x;
    const unsigned it1   = it0 + gsize;

    // item -> float4 address: row = it>>2, slot = it&3;
    // approx at row*8+slot = ((it & ~3)<<1) + (it&3); detail at +4.
    const unsigned ap0 = ((it0 & ~3u) << 1) + (it0 & 3u);
    const unsigned ap1 = ((it1 & ~3u) << 1) + (it1 & 3u);

    if (it1 < n_items) {
        // Fast path (always taken at default shape: 2*gsize == n_items).
        // Four consecutive LDG.128 — keep ALL live until compute (42-reg budget).
        const float4 a0 = xin[ap0];
        const float4 d0 = xin[ap0 + 4];
        const float4 a1 = xin[ap1];
        const float4 d1 = xin[ap1 + 4];

        float4 e0, q0, e1, q1;
        // Interleave the two independent chains.
        e0.x = h00 * a0.x + h10 * d0.x;  e1.x = h00 * a1.x + h10 * d1.x;
        e0.y = h00 * a0.y + h10 * d0.y;  e1.y = h00 * a1.y + h10 * d1.y;
        e0.z = h00 * a0.z + h10 * d0.z;  e1.z = h00 * a1.z + h10 * d1.z;
        e0.w = h00 * a0.w + h10 * d0.w;  e1.w = h00 * a1.w + h10 * d1.w;
        q0.x = h01 * a0.x + h11 * d0.x;  q1.x = h01 * a1.x + h11 * d1.x;
        q0.y = h01 * a0.y + h11 * d0.y;  q1.y = h01 * a1.y + h11 * d1.y;
        q0.z = h01 * a0.z + h11 * d0.z;  q1.z = h01 * a1.z + h11 * d1.z;
        q0.w = h01 * a0.w + h11 * d0.w;  q1.w = h01 * a1.w + h11 * d1.w;

        o[ap0]     = e0;
        o[ap0 + 4] = q0;
        o[ap1]     = e1;
        o[ap1 + 4] = q1;
    } else if (it0 < n_items) {
        // Tail (not reached at default shape).
        const float4 a0 = xin[ap0];
        const float4 d0 = xin[ap0 + 4];
        float4 e0, q0;
        e0.x = h00 * a0.x + h10 * d0.x;  q0.x = h01 * a0.x + h11 * d0.x;
        e0.y = h00 * a0.y + h10 * d0.y;  q0.y = h01 * a0.y + h11 * d0.y;
        e0.z = h00 * a0.z + h10 * d0.z;  q0.z = h01 * a0.z + h11 * d0.z;
        e0.w = h00 * a0.w + h10 * d0.w;  q0.w = h01 * a0.w + h11 * d0.w;
        o[ap0]     = e0;
        o[ap0 + 4] = q0;
    }
}

extern "C" void kernel_launch(void* const* d_in, const int* in_sizes, int n_in,
                              void* d_out, int out_size)
{
    const float4* x = (const float4*)d_in[0];
    const float*  A = (const float*)d_in[1];
    float4* out     = (float4*)d_out;

    // A is (N, N): recover N from its element count (power of two).
    long long a_elems = in_sizes[1];
    long long N = 1;
    while (N * N < a_elems) N <<= 1;          // 4096 at default shape
    const long long M = N >> 1;
    const unsigned highpass_row = (unsigned)(M * N);   // flat index of A[M,0]

    const unsigned n_items = (unsigned)(in_sizes[0] / 8);  // float4-pairs = 524288

    const int threads = 256;
    unsigned blocks = (n_items / 2 + threads - 1) / threads;  // 1024 at default
    if (blocks < 1) blocks = 1;

    idwt_haar_x2_kernel<<<blocks, threads>>>(x, A, out, n_items, highpass_row);
}

// round 9
// speedup vs baseline: 1.0808x; 1.0808x over previous
#include <cuda_runtime.h>

// IDWT1D (Haar synthesis) — 2-tap banded A => streaming butterfly.
//
//   out[b,2i  ,c] = A[0,0]*x[b,i,c] + A[M,0]*x[b,i,C+c]
//   out[b,2i+1,c] = A[0,1]*x[b,i,c] + A[M,1]*x[b,i,C+c]
//
// Row = 32 contiguous floats [approx16|detail16]; the two output rows occupy
// the SAME 32-float span (even half then odd half).
//
// R3..R7 all used a split addressing (each LDG.128 touched 8 half-used 128B
// lines, nL=8) and plateaued at ~8us with every pipe <30%. R8/R9 makes every
// memory instruction DENSE: thread g <-> float4 g. Lane slot s=g&7: s<4 holds
// approx, s>=4 holds detail. Partner exchange via shfl_xor(4) (MIO pipe, no
// L1tex). Each lane writes its own float4 back to the same offset:
//   s<4 : out = h00*a + h10*d   (even row half)
//   s>=4: out = h01*a + h11*d   (odd  row half)
// 2 items/thread (it0=tid, it1=tid+gsize), both streams dense & front-batched.

__global__ void __launch_bounds__(256, 6)
idwt_haar_dense_kernel(const float4* __restrict__ xin,
                       const float* __restrict__ A,
                       float4* __restrict__ o,
                       unsigned n_vec4,          // total float4 count (B*M*8)
                       unsigned highpass_row)    // M*N: flat index of A[M,0]
{
    const float h00 = __ldg(&A[0]);                 // A[0,0]
    const float h01 = __ldg(&A[1]);                 // A[0,1]
    const float h10 = __ldg(&A[highpass_row]);      // A[M,0]
    const float h11 = __ldg(&A[highpass_row + 1]);  // A[M,1]

    const unsigned gsize = gridDim.x * blockDim.x;
    const unsigned g0    = blockIdx.x * blockDim.x + threadIdx.x;
    const unsigned g1    = g0 + gsize;

    // slot within the 8-float4 row; same role for g1 since gsize % 8 == 0.
    const bool isA = (g0 & 4u) == 0u;     // slots 0-3 = approx holder
    const float ta = isA ? h00 : h01;     // tap applied to the approx value
    const float tb = isA ? h10 : h11;     // tap applied to the detail value

    if (g1 < n_vec4) {
        // Fast path (whole warp valid at default shape: 2*gsize == n_vec4).
        const float4 v0 = xin[g0];        // dense: 4 full 128B lines / warp
        const float4 v1 = xin[g1];

        // Partner float4 from lane^4 (same 8-lane row group).
        float4 p0, p1;
        p0.x = __shfl_xor_sync(0xFFFFFFFFu, v0.x, 4);
        p0.y = __shfl_xor_sync(0xFFFFFFFFu, v0.y, 4);
        p0.z = __shfl_xor_sync(0xFFFFFFFFu, v0.z, 4);
        p0.w = __shfl_xor_sync(0xFFFFFFFFu, v0.w, 4);
        p1.x = __shfl_xor_sync(0xFFFFFFFFu, v1.x, 4);
        p1.y = __shfl_xor_sync(0xFFFFFFFFu, v1.y, 4);
        p1.z = __shfl_xor_sync(0xFFFFFFFFu, v1.z, 4);
        p1.w = __shfl_xor_sync(0xFFFFFFFFu, v1.w, 4);

        // approx value / detail value per lane role
        const float4 aa0 = isA ? v0 : p0;
        const float4 dd0 = isA ? p0 : v0;
        const float4 aa1 = isA ? v1 : p1;
        const float4 dd1 = isA ? p1 : v1;

        float4 r0, r1;
        r0.x = ta * aa0.x + tb * dd0.x;   r1.x = ta * aa1.x + tb * dd1.x;
        r0.y = ta * aa0.y + tb * dd0.y;   r1.y = ta * aa1.y + tb * dd1.y;
        r0.z = ta * aa0.z + tb * dd0.z;   r1.z = ta * aa1.z + tb * dd1.z;
        r0.w = ta * aa0.w + tb * dd0.w;   r1.w = ta * aa1.w + tb * dd1.w;

        o[g0] = r0;                        // dense stores, same offsets
        o[g1] = r1;
    } else if (g0 < n_vec4) {
        // Tail (unused at default shape). Rows are 8-float4 aligned, so the
        // whole 8-lane group of g0 is valid together; shuffle stays safe.
        const float4 v0 = xin[g0];
        float4 p0;
        p0.x = __shfl_xor_sync(0xFFFFFFFFu, v0.x, 4);
        p0.y = __shfl_xor_sync(0xFFFFFFFFu, v0.y, 4);
        p0.z = __shfl_xor_sync(0xFFFFFFFFu, v0.z, 4);
        p0.w = __shfl_xor_sync(0xFFFFFFFFu, v0.w, 4);
        const float4 aa0 = isA ? v0 : p0;
        const float4 dd0 = isA ? p0 : v0;
        float4 r0;
        r0.x = ta * aa0.x + tb * dd0.x;
        r0.y = ta * aa0.y + tb * dd0.y;
        r0.z = ta * aa0.z + tb * dd0.z;
        r0.w = ta * aa0.w + tb * dd0.w;
        o[g0] = r0;
    }
}

extern "C" void kernel_launch(void* const* d_in, const int* in_sizes, int n_in,
                              void* d_out, int out_size)
{
    const float4* x = (const float4*)d_in[0];
    const float*  A = (const float*)d_in[1];
    float4* out     = (float4*)d_out;

    // A is (N, N): recover N from its element count (power of two).
    long long a_elems = in_sizes[1];
    long long N = 1;
    while (N * N < a_elems) N <<= 1;          // 4096 at default shape
    const long long M = N >> 1;
    const unsigned highpass_row = (unsigned)(M * N);   // flat index of A[M,0]

    const unsigned n_vec4 = (unsigned)(in_sizes[0] / 4);  // 1048576 at default

    const int threads = 256;
    unsigned blocks = (n_vec4 / 2 + threads - 1) / threads;  // 2048 at default
    if (blocks < 1) blocks = 1;

    idwt_haar_dense_kernel<<<blocks, threads>>>(x, A, out, n_vec4, highpass_row);
}